// round 1
// baseline (speedup 1.0000x reference)
#include <cuda_runtime.h>
#include <cuda_bf16.h>
#include <math.h>

// Problem constants (fixed by the reference)
#define BATCH   4
#define TQ      2048
#define TK      2048
#define DMODEL  1024
#define NHEADS  16
#define HDIM    64
#define MROWS   (BATCH * TQ)   // 8192

// ---------------- scratch (allocation-free rule: __device__ globals) -------
__device__ float g_Q[MROWS * DMODEL];  // (b,h,t,hd)
__device__ float g_K[MROWS * DMODEL];  // (b,h,t,hd)
__device__ float g_V[MROWS * DMODEL];  // (b,h,t,hd)
__device__ float g_O[MROWS * DMODEL];  // (b,t, h*hd) row-major

// ---------------- SGEMM: C = A (M,K) @ W(N,K)^T ----------------------------
// 128x128 block tile, BK=8, 256 threads, 8x8 per-thread microtile.
#define BM 128
#define BN 128
#define BKK 8

template <bool SPLIT_HEADS>
__global__ void __launch_bounds__(256, 2)
sgemm_kernel(const float* __restrict__ A, const float* __restrict__ W,
             float* __restrict__ C, int M, int N, int K)
{
    __shared__ float As[BKK][BM];
    __shared__ float Ws[BKK][BN];

    const int tid = threadIdx.x;
    const int tx  = tid & 15;      // 0..15 -> N direction
    const int ty  = tid >> 4;      // 0..15 -> M direction

    const int bm = blockIdx.y * BM;
    const int bn = blockIdx.x * BN;

    // gmem load mapping: each thread loads one float4 of A and one of W per k-step
    const int lr = tid >> 1;         // 0..127 : row within tile
    const int lk = (tid & 1) * 4;    // 0 or 4 : k offset

    const float* Aptr = A + (size_t)(bm + lr) * K + lk;
    const float* Wptr = W + (size_t)(bn + lr) * K + lk;

    float acc[8][8];
#pragma unroll
    for (int i = 0; i < 8; i++)
#pragma unroll
        for (int j = 0; j < 8; j++) acc[i][j] = 0.f;

    for (int k0 = 0; k0 < K; k0 += BKK) {
        float4 av = *(const float4*)(Aptr + k0);
        float4 wv = *(const float4*)(Wptr + k0);
        __syncthreads();
        As[lk + 0][lr] = av.x; As[lk + 1][lr] = av.y;
        As[lk + 2][lr] = av.z; As[lk + 3][lr] = av.w;
        Ws[lk + 0][lr] = wv.x; Ws[lk + 1][lr] = wv.y;
        Ws[lk + 2][lr] = wv.z; Ws[lk + 3][lr] = wv.w;
        __syncthreads();

#pragma unroll
        for (int kk = 0; kk < BKK; kk++) {
            float a[8], b[8];
            *(float4*)(a)     = *(const float4*)&As[kk][ty * 8];
            *(float4*)(a + 4) = *(const float4*)&As[kk][ty * 8 + 4];
            *(float4*)(b)     = *(const float4*)&Ws[kk][tx * 8];
            *(float4*)(b + 4) = *(const float4*)&Ws[kk][tx * 8 + 4];
#pragma unroll
            for (int i = 0; i < 8; i++)
#pragma unroll
                for (int j = 0; j < 8; j++)
                    acc[i][j] = fmaf(a[i], b[j], acc[i][j]);
        }
    }

    // epilogue
#pragma unroll
    for (int i = 0; i < 8; i++) {
        const int m = bm + ty * 8 + i;
        if (!SPLIT_HEADS) {
            float* cp = C + (size_t)m * N + bn + tx * 8;
            *(float4*)(cp)     = make_float4(acc[i][0], acc[i][1], acc[i][2], acc[i][3]);
            *(float4*)(cp + 4) = make_float4(acc[i][4], acc[i][5], acc[i][6], acc[i][7]);
        } else {
            // (m, n) -> (b, h, t, hd):   m = b*TQ + t, n = h*HDIM + hd
            const int b = m / TQ, t = m % TQ;
            const int n0 = bn + tx * 8;           // stays within one head (8 | 64)
            const int h  = n0 / HDIM;
            const int hd = n0 % HDIM;
            float* cp = C + (((size_t)(b * NHEADS + h) * TQ + t) * HDIM + hd);
            *(float4*)(cp)     = make_float4(acc[i][0], acc[i][1], acc[i][2], acc[i][3]);
            *(float4*)(cp + 4) = make_float4(acc[i][4], acc[i][5], acc[i][6], acc[i][7]);
        }
    }
}

// ---------------- Fused flash-attention (fp32, online softmax) -------------
// 64 queries x 64 keys per tile, 256 threads, 4x4 microtiles.
#define AQ   64
#define AK   64
#define QPAD 68    // padded row stride (floats) for Q / K / P smem tiles

__global__ void __launch_bounds__(256, 2)
attn_kernel(const float* __restrict__ Q, const float* __restrict__ K,
            const float* __restrict__ V, const float* __restrict__ mask,
            const unsigned char* __restrict__ kpm, float* __restrict__ O)
{
    extern __shared__ float sm[];
    float* Qs  = sm;                    // 64 x 68
    float* KPs = sm + AQ * QPAD;        // 64 x 68  (K tile, later reused as P)
    float* Vs  = sm + 2 * AQ * QPAD;    // 64 x 64

    const int tid = threadIdx.x;
    const int tx  = tid & 15;
    const int ty  = tid >> 4;

    const int q0 = blockIdx.x * AQ;
    const int bh = blockIdx.y;          // b*NHEADS + h
    const int b  = bh >> 4;
    const int h  = bh & 15;

    const float* Qb = Q + (size_t)bh * TQ * HDIM;
    const float* Kb = K + (size_t)bh * TK * HDIM;
    const float* Vb = V + (size_t)bh * TK * HDIM;

    // load Q tile (64 x 64)
#pragma unroll
    for (int r = 0; r < 4; r++) {
        int id  = tid + r * 256;        // float4 id, 0..1023
        int row = id >> 4;
        int c4  = (id & 15) * 4;
        float4 v = *(const float4*)&Qb[(size_t)(q0 + row) * HDIM + c4];
        *(float4*)&Qs[row * QPAD + c4] = v;
    }

    float m_i[4], l_i[4], o[4][4];
#pragma unroll
    for (int i = 0; i < 4; i++) {
        m_i[i] = -INFINITY; l_i[i] = 0.f;
#pragma unroll
        for (int j = 0; j < 4; j++) o[i][j] = 0.f;
    }

    const float scale = 0.125f;  // 1/sqrt(64)

    for (int kt = 0; kt < TK / AK; kt++) {
        const int k0 = kt * AK;
        __syncthreads();  // previous PV done before overwriting KPs / Vs
        // load K and V tiles
#pragma unroll
        for (int r = 0; r < 4; r++) {
            int id  = tid + r * 256;
            int row = id >> 4;
            int c4  = (id & 15) * 4;
            float4 kv = *(const float4*)&Kb[(size_t)(k0 + row) * HDIM + c4];
            *(float4*)&KPs[row * QPAD + c4] = kv;
            float4 vv = *(const float4*)&Vb[(size_t)(k0 + row) * HDIM + c4];
            *(float4*)&Vs[row * AK + c4] = vv;
        }
        __syncthreads();

        // S = Q @ K^T
        float s[4][4];
#pragma unroll
        for (int i = 0; i < 4; i++)
#pragma unroll
            for (int j = 0; j < 4; j++) s[i][j] = 0.f;

#pragma unroll
        for (int d4 = 0; d4 < HDIM / 4; d4++) {
            float4 qv[4], kv[4];
#pragma unroll
            for (int i = 0; i < 4; i++)
                qv[i] = *(const float4*)&Qs[(ty * 4 + i) * QPAD + d4 * 4];
#pragma unroll
            for (int j = 0; j < 4; j++)
                kv[j] = *(const float4*)&KPs[(tx * 4 + j) * QPAD + d4 * 4];
#pragma unroll
            for (int i = 0; i < 4; i++)
#pragma unroll
                for (int j = 0; j < 4; j++) {
                    s[i][j] = fmaf(qv[i].x, kv[j].x, s[i][j]);
                    s[i][j] = fmaf(qv[i].y, kv[j].y, s[i][j]);
                    s[i][j] = fmaf(qv[i].z, kv[j].z, s[i][j]);
                    s[i][j] = fmaf(qv[i].w, kv[j].w, s[i][j]);
                }
        }

        // scale + additive mask + key padding mask
        uchar4 pm = *(const uchar4*)&kpm[(size_t)b * TK + k0 + tx * 4];
#pragma unroll
        for (int i = 0; i < 4; i++) {
            const int qg = q0 + ty * 4 + i;
            float4 mv = *(const float4*)&mask[(size_t)qg * TK + k0 + tx * 4];
            s[i][0] = s[i][0] * scale + mv.x;
            s[i][1] = s[i][1] * scale + mv.y;
            s[i][2] = s[i][2] * scale + mv.z;
            s[i][3] = s[i][3] * scale + mv.w;
            if (pm.x) s[i][0] = -INFINITY;
            if (pm.y) s[i][1] = -INFINITY;
            if (pm.z) s[i][2] = -INFINITY;
            if (pm.w) s[i][3] = -INFINITY;
        }

        // online softmax
        float p[4][4];
#pragma unroll
        for (int i = 0; i < 4; i++) {
            float rm = fmaxf(fmaxf(s[i][0], s[i][1]), fmaxf(s[i][2], s[i][3]));
#pragma unroll
            for (int off = 8; off > 0; off >>= 1)
                rm = fmaxf(rm, __shfl_xor_sync(0xffffffffu, rm, off));
            float m_new = fmaxf(m_i[i], rm);
            float alpha, rs = 0.f;
            if (m_new == -INFINITY) {     // fully masked so far
                alpha = 1.f;
#pragma unroll
                for (int j = 0; j < 4; j++) p[i][j] = 0.f;
            } else {
                alpha = (m_i[i] == -INFINITY) ? 0.f : __expf(m_i[i] - m_new);
#pragma unroll
                for (int j = 0; j < 4; j++) {
                    p[i][j] = __expf(s[i][j] - m_new);
                    rs += p[i][j];
                }
            }
#pragma unroll
            for (int off = 8; off > 0; off >>= 1)
                rs += __shfl_xor_sync(0xffffffffu, rs, off);
            l_i[i] = l_i[i] * alpha + rs;
            m_i[i] = m_new;
#pragma unroll
            for (int j = 0; j < 4; j++) o[i][j] *= alpha;
        }

        __syncthreads();  // everyone done reading KPs as K
        // write P into KPs
#pragma unroll
        for (int i = 0; i < 4; i++)
            *(float4*)&KPs[(ty * 4 + i) * QPAD + tx * 4] =
                make_float4(p[i][0], p[i][1], p[i][2], p[i][3]);
        __syncthreads();

        // O += P @ V
#pragma unroll
        for (int j4 = 0; j4 < AK / 4; j4++) {
            float4 pv[4], vv[4];
#pragma unroll
            for (int i = 0; i < 4; i++)
                pv[i] = *(const float4*)&KPs[(ty * 4 + i) * QPAD + j4 * 4];
#pragma unroll
            for (int r = 0; r < 4; r++)
                vv[r] = *(const float4*)&Vs[(j4 * 4 + r) * AK + tx * 4];
#pragma unroll
            for (int i = 0; i < 4; i++) {
                o[i][0] += pv[i].x * vv[0].x + pv[i].y * vv[1].x + pv[i].z * vv[2].x + pv[i].w * vv[3].x;
                o[i][1] += pv[i].x * vv[0].y + pv[i].y * vv[1].y + pv[i].z * vv[2].y + pv[i].w * vv[3].y;
                o[i][2] += pv[i].x * vv[0].z + pv[i].y * vv[1].z + pv[i].z * vv[2].z + pv[i].w * vv[3].z;
                o[i][3] += pv[i].x * vv[0].w + pv[i].y * vv[1].w + pv[i].z * vv[2].w + pv[i].w * vv[3].w;
            }
        }
    }

    // finalize and write O in (b, t, h*hd) row-major
#pragma unroll
    for (int i = 0; i < 4; i++) {
        float inv = (l_i[i] > 0.f) ? (1.f / l_i[i]) : 0.f;
        const int t = q0 + ty * 4 + i;
        float* op = O + ((size_t)(b * TQ + t)) * DMODEL + h * HDIM + tx * 4;
        *(float4*)op = make_float4(o[i][0] * inv, o[i][1] * inv, o[i][2] * inv, o[i][3] * inv);
    }
}

// ---------------- launch ----------------------------------------------------
extern "C" void kernel_launch(void* const* d_in, const int* in_sizes, int n_in,
                              void* d_out, int out_size)
{
    const float* x_q  = (const float*)d_in[0];
    const float* x_kv = (const float*)d_in[1];
    const float* amask = (const float*)d_in[2];
    const unsigned char* kpm = (const unsigned char*)d_in[3];
    const float* Wq = (const float*)d_in[4];
    const float* Wk = (const float*)d_in[5];
    const float* Wv = (const float*)d_in[6];
    const float* Wo = (const float*)d_in[7];
    float* out = (float*)d_out;

    float *qP, *kP, *vP, *oP;
    cudaGetSymbolAddress((void**)&qP, g_Q);
    cudaGetSymbolAddress((void**)&kP, g_K);
    cudaGetSymbolAddress((void**)&vP, g_V);
    cudaGetSymbolAddress((void**)&oP, g_O);

    dim3 gblk(DMODEL / BN, MROWS / BM);   // (8, 64)
    sgemm_kernel<true><<<gblk, 256>>>(x_q,  Wq, qP, MROWS, DMODEL, DMODEL);
    sgemm_kernel<true><<<gblk, 256>>>(x_kv, Wk, kP, MROWS, DMODEL, DMODEL);
    sgemm_kernel<true><<<gblk, 256>>>(x_kv, Wv, vP, MROWS, DMODEL, DMODEL);

    const int attn_smem = (2 * AQ * QPAD + AQ * AK) * (int)sizeof(float);  // 51200
    cudaFuncSetAttribute(attn_kernel, cudaFuncAttributeMaxDynamicSharedMemorySize, attn_smem);
    dim3 ga(TQ / AQ, BATCH * NHEADS);     // (32, 64)
    attn_kernel<<<ga, 256, attn_smem>>>(qP, kP, vP, amask, kpm, oP);

    sgemm_kernel<false><<<gblk, 256>>>(oP, Wo, out, MROWS, DMODEL, DMODEL);
}

// round 2
// speedup vs baseline: 3.9548x; 3.9548x over previous
#include <cuda_runtime.h>
#include <math.h>

#define BATCH   4
#define TQ      2048
#define TK      2048
#define DMODEL  1024
#define NHEADS  16
#define HDIM    64
#define MROWS   (BATCH * TQ)   // 8192

// ---------------- scratch (allocation-free rule: __device__ globals) -------
__device__ float g_Q[MROWS * DMODEL];  // (b,h,t,hd)
__device__ float g_K[MROWS * DMODEL];  // (b,h,t,hd)
__device__ float g_V[MROWS * DMODEL];  // (b,h,t,hd)
__device__ float g_O[MROWS * DMODEL];  // (b,t,dmodel)

// ---------------- helpers ---------------------------------------------------
__device__ __forceinline__ unsigned f2tf(float x) {
    unsigned r;
    asm("cvt.rna.tf32.f32 %0, %1;" : "=r"(r) : "f"(x));
    return r;
}

__device__ __forceinline__ void mma_tf32(float* d, const unsigned* a, const unsigned* b) {
    asm volatile(
        "mma.sync.aligned.m16n8k8.row.col.f32.tf32.tf32.f32 "
        "{%0,%1,%2,%3}, {%4,%5,%6,%7}, {%8,%9}, {%0,%1,%2,%3};"
        : "+f"(d[0]), "+f"(d[1]), "+f"(d[2]), "+f"(d[3])
        : "r"(a[0]), "r"(a[1]), "r"(a[2]), "r"(a[3]), "r"(b[0]), "r"(b[1]));
}

__device__ __forceinline__ void cp16(void* smem_dst, const void* gmem_src) {
    unsigned s = (unsigned)__cvta_generic_to_shared(smem_dst);
    asm volatile("cp.async.cg.shared.global [%0], [%1], 16;" :: "r"(s), "l"(gmem_src));
}

// ---------------- tf32 GEMM: C = A(M,K) @ W(N,K)^T --------------------------
#define BM   128
#define BN   128
#define BK   32
#define SSTR 36     // smem row stride (floats): 36 % 32 == 4 -> conflict-free frags

template <bool SPLIT_HEADS>
__global__ void __launch_bounds__(256, 2)
gemm_tf32(const float* __restrict__ A, const float* __restrict__ W,
          float* __restrict__ C)
{
    extern __shared__ float sm[];
    float* As = sm;                       // [2][BM][SSTR]
    float* Ws = sm + 2 * BM * SSTR;       // [2][BN][SSTR]

    const int tid  = threadIdx.x;
    const int lane = tid & 31;
    const int warp = tid >> 5;
    const int wm   = warp >> 2;           // 0..1
    const int wn   = warp & 3;            // 0..3
    const int bm   = blockIdx.y * BM;
    const int bn   = blockIdx.x * BN;
    const int lr   = lane >> 2;           // 0..7
    const int lc   = lane & 3;            // 0..3

    float acc[4][4][4];
#pragma unroll
    for (int i = 0; i < 4; i++)
#pragma unroll
        for (int j = 0; j < 4; j++)
#pragma unroll
            for (int c = 0; c < 4; c++) acc[i][j][c] = 0.f;

    const int NIT = DMODEL / BK;  // 32

    auto load_stage = [&](int st, int k0) {
#pragma unroll
        for (int r = 0; r < 4; r++) {
            int id = tid + r * 256;
            int m  = id >> 3;
            int k4 = (id & 7) * 4;
            cp16(&As[(st * BM + m) * SSTR + k4], &A[(size_t)(bm + m) * DMODEL + k0 + k4]);
            cp16(&Ws[(st * BN + m) * SSTR + k4], &W[(size_t)(bn + m) * DMODEL + k0 + k4]);
        }
        asm volatile("cp.async.commit_group;");
    };

    load_stage(0, 0);

    for (int it = 0; it < NIT; it++) {
        if (it + 1 < NIT) {
            load_stage((it + 1) & 1, (it + 1) * BK);
            asm volatile("cp.async.wait_group 1;");
        } else {
            asm volatile("cp.async.wait_group 0;");
        }
        __syncthreads();
        const float* Ab = &As[(it & 1) * BM * SSTR];
        const float* Wb = &Ws[(it & 1) * BN * SSTR];

#pragma unroll
        for (int kk = 0; kk < 4; kk++) {
            const int k = kk * 8;
            unsigned af[4][4], bf[4][2];
#pragma unroll
            for (int mf = 0; mf < 4; mf++) {
                const float* p = &Ab[(wm * 64 + mf * 16 + lr) * SSTR + k + lc];
                af[mf][0] = f2tf(p[0]);
                af[mf][1] = f2tf(p[8 * SSTR]);
                af[mf][2] = f2tf(p[4]);
                af[mf][3] = f2tf(p[8 * SSTR + 4]);
            }
#pragma unroll
            for (int nf = 0; nf < 4; nf++) {
                const float* p = &Wb[(wn * 32 + nf * 8 + lr) * SSTR + k + lc];
                bf[nf][0] = f2tf(p[0]);
                bf[nf][1] = f2tf(p[4]);
            }
#pragma unroll
            for (int mf = 0; mf < 4; mf++)
#pragma unroll
                for (int nf = 0; nf < 4; nf++)
                    mma_tf32(acc[mf][nf], af[mf], bf[nf]);
        }
        __syncthreads();
    }

    // epilogue
#pragma unroll
    for (int mf = 0; mf < 4; mf++) {
#pragma unroll
        for (int half = 0; half < 2; half++) {
            const int m = bm + wm * 64 + mf * 16 + lr + half * 8;
#pragma unroll
            for (int nf = 0; nf < 4; nf++) {
                const int n = bn + wn * 32 + nf * 8 + 2 * lc;
                float2 v = make_float2(acc[mf][nf][half * 2], acc[mf][nf][half * 2 + 1]);
                if (!SPLIT_HEADS) {
                    *(float2*)&C[(size_t)m * DMODEL + n] = v;
                } else {
                    const int b = m >> 11, t = m & 2047;   // TQ = 2048
                    const int h = n >> 6,  hd = n & 63;    // HDIM = 64
                    *(float2*)&C[(((size_t)(b * NHEADS + h) * TQ + t) << 6) + hd] = v;
                }
            }
        }
    }
}

// ---------------- fused attention with tf32 mma ------------------------------
// block: 64 q-rows, 4 warps; each warp owns 16 complete rows.
#define AQ   64
#define QSTR 68   // 68 % 32 == 4
#define VSTR 72   // 72 % 32 == 8

__global__ void __launch_bounds__(128, 3)
attn_tf32(const float* __restrict__ Q, const float* __restrict__ K,
          const float* __restrict__ V, const float* __restrict__ mask,
          const unsigned char* __restrict__ kpm, float* __restrict__ O)
{
    extern __shared__ float sm[];
    float* Qs = sm;                      // 64 x 68
    float* Ks = Qs + AQ * QSTR;          // 64 x 68
    float* Vs = Ks + AQ * QSTR;          // 64 x 72
    float* Ps = Vs + AQ * VSTR;          // 64 x 68

    const int tid  = threadIdx.x;
    const int lane = tid & 31;
    const int warp = tid >> 5;
    const int lr   = lane >> 2;          // 0..7
    const int lc   = lane & 3;           // 0..3

    const int q0 = blockIdx.x * AQ;
    const int bh = blockIdx.y;
    const int b  = bh >> 4;
    const int h  = bh & 15;

    const float* Qb = Q + (size_t)bh * TQ * HDIM;
    const float* Kb = K + (size_t)bh * TK * HDIM;
    const float* Vb = V + (size_t)bh * TK * HDIM;

    // load Q tile, pre-scaled by 1/sqrt(HDIM), converted to tf32 bits
#pragma unroll
    for (int r = 0; r < 8; r++) {
        int id = tid + r * 128;          // 1024 float4 slots: 64 rows x 16
        int row = id >> 4, c4 = (id & 15) * 4;
        float4 v = *(const float4*)&Qb[(size_t)(q0 + row) * HDIM + c4];
        float* d = &Qs[row * QSTR + c4];
        d[0] = __uint_as_float(f2tf(v.x * 0.125f));
        d[1] = __uint_as_float(f2tf(v.y * 0.125f));
        d[2] = __uint_as_float(f2tf(v.z * 0.125f));
        d[3] = __uint_as_float(f2tf(v.w * 0.125f));
    }
    __syncthreads();

    // hoist Q fragments to registers (warp rows 16*warp .. +15, k = 0..63)
    unsigned qf[8][4];
#pragma unroll
    for (int kk = 0; kk < 8; kk++) {
        const float* p = &Qs[(warp * 16 + lr) * QSTR + kk * 8 + lc];
        qf[kk][0] = __float_as_uint(p[0]);
        qf[kk][1] = __float_as_uint(p[8 * QSTR]);
        qf[kk][2] = __float_as_uint(p[4]);
        qf[kk][3] = __float_as_uint(p[8 * QSTR + 4]);
    }

    float m_i[2] = {-INFINITY, -INFINITY};
    float l_i[2] = {0.f, 0.f};
    float o[8][4];
#pragma unroll
    for (int nf = 0; nf < 8; nf++)
#pragma unroll
        for (int c = 0; c < 4; c++) o[nf][c] = 0.f;

    for (int kt = 0; kt < TK / 64; kt++) {
        const int k0 = kt * 64;
        __syncthreads();   // previous iteration's Ks/Vs reads complete
#pragma unroll
        for (int r = 0; r < 8; r++) {
            int id = tid + r * 128;
            int row = id >> 4, c4 = (id & 15) * 4;
            float4 kv = *(const float4*)&Kb[(size_t)(k0 + row) * HDIM + c4];
            float* dk = &Ks[row * QSTR + c4];
            dk[0] = __uint_as_float(f2tf(kv.x));
            dk[1] = __uint_as_float(f2tf(kv.y));
            dk[2] = __uint_as_float(f2tf(kv.z));
            dk[3] = __uint_as_float(f2tf(kv.w));
            float4 vv = *(const float4*)&Vb[(size_t)(k0 + row) * HDIM + c4];
            float* dv = &Vs[row * VSTR + c4];
            dv[0] = __uint_as_float(f2tf(vv.x));
            dv[1] = __uint_as_float(f2tf(vv.y));
            dv[2] = __uint_as_float(f2tf(vv.z));
            dv[3] = __uint_as_float(f2tf(vv.w));
        }
        __syncthreads();

        // S = Qs @ Ks^T  (rows: warp-private 16; cols: 64)
        float s[8][4];
#pragma unroll
        for (int nf = 0; nf < 8; nf++)
#pragma unroll
            for (int c = 0; c < 4; c++) s[nf][c] = 0.f;

#pragma unroll
        for (int kk = 0; kk < 8; kk++) {
#pragma unroll
            for (int nf = 0; nf < 8; nf++) {
                unsigned bf[2];
                const float* p = &Ks[(nf * 8 + lr) * QSTR + kk * 8 + lc];
                bf[0] = __float_as_uint(p[0]);
                bf[1] = __float_as_uint(p[4]);
                mma_tf32(s[nf], qf[kk], bf);
            }
        }

        // masks + online softmax (per row-half; rows are warp/quad-local)
#pragma unroll
        for (int half = 0; half < 2; half++) {
            const int qg = q0 + warp * 16 + lr + half * 8;
            float mx = -INFINITY;
#pragma unroll
            for (int nf = 0; nf < 8; nf++) {
                const size_t col = (size_t)k0 + nf * 8 + 2 * lc;
                float2 mv = *(const float2*)&mask[(size_t)qg * TK + col];
                uchar2 kp = *(const uchar2*)&kpm[(size_t)b * TK + col];
                float v0 = s[nf][half * 2]     + mv.x;
                float v1 = s[nf][half * 2 + 1] + mv.y;
                if (kp.x) v0 = -INFINITY;
                if (kp.y) v1 = -INFINITY;
                s[nf][half * 2]     = v0;
                s[nf][half * 2 + 1] = v1;
                mx = fmaxf(mx, fmaxf(v0, v1));
            }
            mx = fmaxf(mx, __shfl_xor_sync(0xffffffffu, mx, 1));
            mx = fmaxf(mx, __shfl_xor_sync(0xffffffffu, mx, 2));
            float mnew = fmaxf(m_i[half], mx);
            float alpha, rs = 0.f;
            if (mnew == -INFINITY) {
                alpha = 1.f;
#pragma unroll
                for (int nf = 0; nf < 8; nf++) {
                    s[nf][half * 2] = 0.f;
                    s[nf][half * 2 + 1] = 0.f;
                }
            } else {
                alpha = (m_i[half] == -INFINITY) ? 0.f : __expf(m_i[half] - mnew);
#pragma unroll
                for (int nf = 0; nf < 8; nf++) {
                    float p0 = __expf(s[nf][half * 2]     - mnew);
                    float p1 = __expf(s[nf][half * 2 + 1] - mnew);
                    s[nf][half * 2]     = p0;
                    s[nf][half * 2 + 1] = p1;
                    rs += p0 + p1;
                }
            }
            rs += __shfl_xor_sync(0xffffffffu, rs, 1);
            rs += __shfl_xor_sync(0xffffffffu, rs, 2);
            l_i[half] = l_i[half] * alpha + rs;
            m_i[half] = mnew;
#pragma unroll
            for (int nf = 0; nf < 8; nf++) {
                o[nf][half * 2]     *= alpha;
                o[nf][half * 2 + 1] *= alpha;
            }
        }

        // stage P (tf32) into warp-private rows of Ps
#pragma unroll
        for (int half = 0; half < 2; half++) {
            const int row = warp * 16 + lr + half * 8;
#pragma unroll
            for (int nf = 0; nf < 8; nf++) {
                float2 pv;
                pv.x = __uint_as_float(f2tf(s[nf][half * 2]));
                pv.y = __uint_as_float(f2tf(s[nf][half * 2 + 1]));
                *(float2*)&Ps[row * QSTR + nf * 8 + 2 * lc] = pv;
            }
        }
        __syncwarp();

        // O += P @ V
#pragma unroll
        for (int kk = 0; kk < 8; kk++) {
            unsigned af[4];
            const float* pa = &Ps[(warp * 16 + lr) * QSTR + kk * 8 + lc];
            af[0] = __float_as_uint(pa[0]);
            af[1] = __float_as_uint(pa[8 * QSTR]);
            af[2] = __float_as_uint(pa[4]);
            af[3] = __float_as_uint(pa[8 * QSTR + 4]);
#pragma unroll
            for (int nf = 0; nf < 8; nf++) {
                unsigned bf[2];
                const float* pb = &Vs[(kk * 8 + lc) * VSTR + nf * 8 + lr];
                bf[0] = __float_as_uint(pb[0]);
                bf[1] = __float_as_uint(pb[4 * VSTR]);
                mma_tf32(o[nf], af, bf);
            }
        }
    }

    // finalize: write to g_O in (b, t, dmodel) layout
#pragma unroll
    for (int half = 0; half < 2; half++) {
        const float inv = (l_i[half] > 0.f) ? (1.f / l_i[half]) : 0.f;
        const int t = q0 + warp * 16 + lr + half * 8;
#pragma unroll
        for (int nf = 0; nf < 8; nf++) {
            float2 v = make_float2(o[nf][half * 2] * inv, o[nf][half * 2 + 1] * inv);
            *(float2*)&O[((size_t)(b * TQ + t)) * DMODEL + h * HDIM + nf * 8 + 2 * lc] = v;
        }
    }
}

// ---------------- launch ------------------------------------------------------
extern "C" void kernel_launch(void* const* d_in, const int* in_sizes, int n_in,
                              void* d_out, int out_size)
{
    const float* x_q   = (const float*)d_in[0];
    const float* x_kv  = (const float*)d_in[1];
    const float* amask = (const float*)d_in[2];
    const unsigned char* kpm = (const unsigned char*)d_in[3];
    const float* Wq = (const float*)d_in[4];
    const float* Wk = (const float*)d_in[5];
    const float* Wv = (const float*)d_in[6];
    const float* Wo = (const float*)d_in[7];
    float* out = (float*)d_out;

    float *qP, *kP, *vP, *oP;
    cudaGetSymbolAddress((void**)&qP, g_Q);
    cudaGetSymbolAddress((void**)&kP, g_K);
    cudaGetSymbolAddress((void**)&vP, g_V);
    cudaGetSymbolAddress((void**)&oP, g_O);

    const int gemm_smem = 2 * (BM + BN) * SSTR * (int)sizeof(float);   // 73728
    cudaFuncSetAttribute(gemm_tf32<true>,  cudaFuncAttributeMaxDynamicSharedMemorySize, gemm_smem);
    cudaFuncSetAttribute(gemm_tf32<false>, cudaFuncAttributeMaxDynamicSharedMemorySize, gemm_smem);

    dim3 gblk(DMODEL / BN, MROWS / BM);   // (8, 64)
    gemm_tf32<true><<<gblk, 256, gemm_smem>>>(x_q,  Wq, qP);
    gemm_tf32<true><<<gblk, 256, gemm_smem>>>(x_kv, Wk, kP);
    gemm_tf32<true><<<gblk, 256, gemm_smem>>>(x_kv, Wv, vP);

    const int attn_smem = (3 * AQ * QSTR + AQ * VSTR) * (int)sizeof(float);  // 70656
    cudaFuncSetAttribute(attn_tf32, cudaFuncAttributeMaxDynamicSharedMemorySize, attn_smem);
    dim3 ga(TQ / AQ, BATCH * NHEADS);     // (32, 64)
    attn_tf32<<<ga, 128, attn_smem>>>(qP, kP, vP, amask, kpm, oP);

    gemm_tf32<false><<<gblk, 256, gemm_smem>>>(oP, Wo, out);
}